// round 8
// baseline (speedup 1.0000x reference)
#include <cuda_runtime.h>
#include <cuda_bf16.h>
#include <cstdint>

#define N_NODES 50000
#define N_EDGES 1600000
#define DIM 128
#define NREL 24
#define NBASE 8
#define KTA 1024               // T width (basis part only)
#define KTOT 1152              // full K: 1024 basis + 128 root
#define BK 32
#define NKT32 (KTOT / BK)      // 36
#define NKT_T (KTA / BK)       // 32 tiles from T, rest from h
#define CHUNK 12800            // L2-resident producer/consumer chunk (x128)

// ---------------- scratch ----------------
__device__ int   g_cnt_node[N_NODES + 1];
__device__ int   g_row_ptr [N_NODES + 1];
__device__ int   g_cursor  [N_NODES];
__device__ int   g_cnt_nr  [N_NODES * NREL];
__device__ int   g_sorted  [N_EDGES];
__device__ int   g_blk     [64];
__device__ __align__(16) float g_h0[N_NODES * DIM];
__device__ __align__(16) float g_h1[N_NODES * DIM];
__device__ __align__(16) float g_T [(size_t)N_NODES * KTA];    // 204.8 MB
__device__ __align__(16) float g_Bp1[KTOT * DIM];              // tf32-rounded [k][n]
__device__ __align__(16) float g_Bp2[KTOT * DIM];

// ---------------- helpers ----------------
__device__ __forceinline__ uint32_t smem_u32(const void* p) {
    uint32_t a;
    asm("{ .reg .u64 t; cvta.to.shared.u64 t, %1; cvt.u32.u64 %0, t; }"
        : "=r"(a) : "l"(p));
    return a;
}
__device__ __forceinline__ float tf32r(float x) {
    uint32_t u;
    asm("cvt.rna.tf32.f32 %0, %1;" : "=r"(u) : "f"(x));
    return __uint_as_float(u);
}
__device__ __forceinline__ void cp16(uint32_t dst, const void* src, int sz) {
    asm volatile("cp.async.cg.shared.global [%0], [%1], 16, %2;"
                 :: "r"(dst), "l"(src), "r"(sz) : "memory");
}
#define CP_COMMIT() asm volatile("cp.async.commit_group;" ::: "memory")
#define CP_WAIT1()  asm volatile("cp.async.wait_group 1;" ::: "memory")
#define CP_WAIT0()  asm volatile("cp.async.wait_group 0;" ::: "memory")

__device__ __forceinline__ void mma_tf32(float c[4], const uint32_t a[4],
                                         uint32_t b0, uint32_t b1) {
    asm volatile(
        "mma.sync.aligned.m16n8k8.row.col.f32.tf32.tf32.f32 "
        "{%0,%1,%2,%3}, {%4,%5,%6,%7}, {%8,%9}, {%0,%1,%2,%3};\n"
        : "+f"(c[0]), "+f"(c[1]), "+f"(c[2]), "+f"(c[3])
        : "r"(a[0]), "r"(a[1]), "r"(a[2]), "r"(a[3]), "r"(b0), "r"(b1));
}

// packed fp32x2 FMA (Blackwell FFMA2): d = a*b + d, elementwise on pairs
__device__ __forceinline__ void ffma2(unsigned long long& d,
                                      unsigned long long a,
                                      unsigned long long b) {
    asm("fma.rn.f32x2 %0, %1, %2, %0;" : "+l"(d) : "l"(a), "l"(b));
}
__device__ __forceinline__ unsigned long long pack2(float lo, float hi) {
    unsigned long long p;
    asm("mov.b64 %0, {%1, %2};" : "=l"(p) : "f"(lo), "f"(hi));
    return p;
}
__device__ __forceinline__ void unpack2(unsigned long long p, float& lo, float& hi) {
    asm("mov.b64 {%0, %1}, %2;" : "=f"(lo), "=f"(hi) : "l"(p));
}

// ---------------- graph preprocessing ----------------

__global__ void zero_nr_kernel() {
    int total = N_NODES * NREL;
    for (int i = blockIdx.x * blockDim.x + threadIdx.x; i < total;
         i += gridDim.x * blockDim.x)
        g_cnt_nr[i] = 0;
}

__global__ void hist_kernel(const int* __restrict__ e_dst,
                            const int* __restrict__ e_typ, int E) {
    for (int e = blockIdx.x * blockDim.x + threadIdx.x; e < E;
         e += gridDim.x * blockDim.x)
        atomicAdd(&g_cnt_nr[e_dst[e] * NREL + e_typ[e]], 1);
}

__global__ void csr_part1() {
    int n = blockIdx.x * 1024 + threadIdx.x;
    int v = 0;
    if (n < N_NODES) {
        const int* p = &g_cnt_nr[n * NREL];
        #pragma unroll
        for (int t = 0; t < NREL; t++) v += p[t];
        g_cnt_node[n] = v;
    }
    __shared__ int ws[32];
    int lane = threadIdx.x & 31, wid = threadIdx.x >> 5;
    int x = v;
    #pragma unroll
    for (int d = 16; d > 0; d >>= 1) x += __shfl_down_sync(0xffffffffu, x, d);
    if (lane == 0) ws[wid] = x;
    __syncthreads();
    if (wid == 0) {
        int s = ws[lane];
        #pragma unroll
        for (int d = 16; d > 0; d >>= 1) s += __shfl_down_sync(0xffffffffu, s, d);
        if (lane == 0) g_blk[blockIdx.x] = s;
    }
}

__global__ void csr_part2(int nblk) {
    if (threadIdx.x == 0) {
        int s = 0;
        for (int i = 0; i < nblk; i++) { int t = g_blk[i]; g_blk[i] = s; s += t; }
    }
}

__global__ void csr_part3() {
    __shared__ int ws[32];
    int tid = threadIdx.x, lane = tid & 31, wid = tid >> 5;
    int n = blockIdx.x * 1024 + tid;
    int v = (n < N_NODES) ? g_cnt_node[n] : 0;
    int x = v;
    #pragma unroll
    for (int d = 1; d < 32; d <<= 1) {
        int y = __shfl_up_sync(0xffffffffu, x, d);
        if (lane >= d) x += y;
    }
    if (lane == 31) ws[wid] = x;
    __syncthreads();
    if (wid == 0) {
        int s = ws[lane];
        #pragma unroll
        for (int d = 1; d < 32; d <<= 1) {
            int y = __shfl_up_sync(0xffffffffu, s, d);
            if (lane >= d) s += y;
        }
        ws[lane] = s;
    }
    __syncthreads();
    int off = (wid > 0 ? ws[wid - 1] : 0) + g_blk[blockIdx.x];
    int excl = x - v + off;
    if (n < N_NODES) { g_row_ptr[n] = excl; g_cursor[n] = excl; }
    if (n == N_NODES - 1) g_row_ptr[N_NODES] = excl + v;
}

__global__ void scatter_kernel(const int* __restrict__ e_src,
                               const int* __restrict__ e_dst,
                               const int* __restrict__ e_typ, int E) {
    for (int e = blockIdx.x * blockDim.x + threadIdx.x; e < E;
         e += gridDim.x * blockDim.x) {
        int pos = atomicAdd(&g_cursor[e_dst[e]], 1);
        g_sorted[pos] = (e_src[e] << 5) | e_typ[e];
    }
}

__global__ void embed_kernel(const int* __restrict__ x,
                             const float* __restrict__ table) {
    int n = blockIdx.x, i = threadIdx.x;
    g_h0[n * DIM + i] = table[(size_t)x[n] * DIM + i];
}

// Bp[k][n] = tf32_round(k<1024 ? bases[k][n] : root[k-1024][n])
__global__ void prep_b_kernel(const float* __restrict__ bases,
                              const float* __restrict__ root,
                              float* __restrict__ Bp) {
    int k = blockIdx.x, n = threadIdx.x;
    float v = (k < NBASE * DIM) ? bases[k * DIM + n]
                                : root[(k - NBASE * DIM) * DIM + n];
    Bp[k * DIM + n] = tf32r(v);
}

// ---------------- aggregation: 1 CTA/node, 64 lanes x 2 features ------
__global__ void agg_kernel(const float* __restrict__ h,
                           const float* __restrict__ comp, int n0) {
    __shared__ unsigned long long s_w2[NREL * NBASE];   // (w,w) pairs
    __shared__ float s_invc[NREL];
    int n = n0 + blockIdx.x, t = threadIdx.x;   // t in [0,64)
    if (t < NREL) {
        int c = g_cnt_nr[n * NREL + t];
        s_invc[t] = 1.0f / fmaxf((float)c, 1.0f);
    }
    __syncthreads();
    for (int idx = t; idx < NREL * NBASE; idx += 64) {
        float w = comp[idx] * s_invc[idx >> 3];
        s_w2[idx] = pack2(w, w);
    }
    __syncthreads();

    unsigned long long acc[NBASE];
    #pragma unroll
    for (int b = 0; b < NBASE; b++) acc[b] = 0ull;

    const unsigned long long* h2 = (const unsigned long long*)h;  // row = 64 pairs

    int s = g_row_ptr[n], e = g_row_ptr[n + 1];
    int i = s;
    for (; i + 8 <= e; i += 8) {
        int p[8];
        unsigned long long v[8];
        #pragma unroll
        for (int u = 0; u < 8; u++) p[u] = g_sorted[i + u];
        #pragma unroll
        for (int u = 0; u < 8; u++)
            v[u] = __ldg(&h2[(size_t)(p[u] >> 5) * 64 + t]);
        #pragma unroll
        for (int u = 0; u < 8; u++) {
            const unsigned long long* wr = &s_w2[(p[u] & 31) * NBASE];
            #pragma unroll
            for (int b = 0; b < NBASE; b++) ffma2(acc[b], v[u], wr[b]);
        }
    }
    for (; i < e; i++) {
        int p = g_sorted[i];
        unsigned long long v = __ldg(&h2[(size_t)(p >> 5) * 64 + t]);
        const unsigned long long* wr = &s_w2[(p & 31) * NBASE];
        #pragma unroll
        for (int b = 0; b < NBASE; b++) ffma2(acc[b], v, wr[b]);
    }

    float* o = g_T + (size_t)n * KTA + 2 * t;
    #pragma unroll
    for (int b = 0; b < NBASE; b++) {
        float lo, hi;
        unpack2(acc[b], lo, hi);
        *(float2*)&o[b * DIM] = make_float2(tf32r(lo), tf32r(hi));
    }
}

// ---------------- tf32 mma.sync GEMM with cp.async double buffer ------
// out[M,128] = [T | h][M,1152] @ Bp[1152,128] + bias (opt relu)
#define AS_STRIDE 36
#define BS_STRIDE 136
#define AS_FLOATS (128 * AS_STRIDE)          // per stage
#define BS_FLOATS (BK * BS_STRIDE)
#define GEMM_SMEM ((2 * AS_FLOATS + 2 * BS_FLOATS) * 4)   // 71,680 B

__global__ __launch_bounds__(256)
void gemm_tc(const float* __restrict__ A,      // T, width KTA
             const float* __restrict__ Hin,    // h, width 128 (root chunk)
             const float* __restrict__ Bp,
             const float* __restrict__ bias,
             float* __restrict__ out, int M, int doRelu, int mOff) {
    extern __shared__ __align__(16) uint32_t smbuf[];
    uint32_t* AsBase = smbuf;                   // 2 stages
    uint32_t* BsBase = smbuf + 2 * AS_FLOATS;

    int tid  = threadIdx.x;
    int lane = tid & 31;
    int wid  = tid >> 5;
    int wm = (wid >> 1) * 32;     // warp m offset
    int wn = (wid & 1) * 64;      // warp n offset
    int g  = lane >> 2;           // 0..7
    int tg = lane & 3;            // 0..3
    int m0 = mOff + blockIdx.x * 128;

    // cp.async thread mapping
    int aRow  = tid >> 1;                // 0..127
    int aCol0 = (tid & 1) * 16;          // 0 or 16 (floats)
    int bRow  = tid >> 3;                // 0..31
    int bCol0 = (tid & 7) * 16;          // 0..112 (floats)

    int aSz = (m0 + aRow < M) ? 16 : 0;  // zero-fill OOB rows
    const float* aSrcT = A   + (size_t)(m0 + aRow) * KTA + aCol0;
    const float* aSrcH = Hin + (size_t)(m0 + aRow) * DIM + aCol0;
    uint32_t aDst0 = smem_u32(&AsBase[aRow * AS_STRIDE + aCol0]);
    uint32_t bDst0 = smem_u32(&BsBase[bRow * BS_STRIDE + bCol0]);

    float acc[2][8][4];
    #pragma unroll
    for (int mt = 0; mt < 2; mt++) {
        #pragma unroll
        for (int nt = 0; nt < 8; nt++) {
            #pragma unroll
            for (int q = 0; q < 4; q++) acc[mt][nt][q] = 0.0f;
        }
    }

    // issue stage for k-tile kt into buffer s
    auto issue = [&](int s, int kt) {
        const float* as = (kt < NKT_T) ? (aSrcT + kt * BK)
                                       : (aSrcH + (kt - NKT_T) * BK);
        uint32_t ad = aDst0 + s * AS_FLOATS * 4;
        #pragma unroll
        for (int c = 0; c < 4; c++)
            cp16(ad + c * 16, as + c * 4, aSz);
        const float* bs = Bp + (size_t)(kt * BK + bRow) * DIM + bCol0;
        uint32_t bd = bDst0 + s * BS_FLOATS * 4;
        #pragma unroll
        for (int c = 0; c < 4; c++)
            cp16(bd + c * 16, bs + c * 4, 16);
        CP_COMMIT();
    };

    issue(0, 0);

    for (int kt = 0; kt < NKT32; kt++) {
        int cur = kt & 1;
        if (kt + 1 < NKT32) {
            issue((kt + 1) & 1, kt + 1);
            CP_WAIT1();
        } else {
            CP_WAIT0();
        }
        __syncthreads();

        const uint32_t* Asb = AsBase + cur * AS_FLOATS;
        const uint32_t* Bsb = BsBase + cur * BS_FLOATS;

        #pragma unroll
        for (int ks = 0; ks < BK; ks += 8) {
            uint32_t af[2][4];
            #pragma unroll
            for (int mt = 0; mt < 2; mt++) {
                int mm = wm + mt * 16 + g;
                af[mt][0] = Asb[(mm)     * AS_STRIDE + ks + tg];
                af[mt][1] = Asb[(mm + 8) * AS_STRIDE + ks + tg];
                af[mt][2] = Asb[(mm)     * AS_STRIDE + ks + tg + 4];
                af[mt][3] = Asb[(mm + 8) * AS_STRIDE + ks + tg + 4];
            }
            #pragma unroll
            for (int nt = 0; nt < 8; nt++) {
                int n0 = wn + nt * 8 + g;
                uint32_t b0 = Bsb[(ks + tg)     * BS_STRIDE + n0];
                uint32_t b1 = Bsb[(ks + tg + 4) * BS_STRIDE + n0];
                mma_tf32(acc[0][nt], af[0], b0, b1);
                mma_tf32(acc[1][nt], af[1], b0, b1);
            }
        }
        __syncthreads();
    }

    // epilogue: bias + optional relu
    #pragma unroll
    for (int mt = 0; mt < 2; mt++) {
        int r0 = m0 + wm + mt * 16 + g;
        #pragma unroll
        for (int nt = 0; nt < 8; nt++) {
            int col = wn + nt * 8 + 2 * tg;
            float bx = __ldg(&bias[col]), by = __ldg(&bias[col + 1]);
            float v0 = acc[mt][nt][0] + bx, v1 = acc[mt][nt][1] + by;
            float v2 = acc[mt][nt][2] + bx, v3 = acc[mt][nt][3] + by;
            if (doRelu) {
                v0 = fmaxf(v0, 0.f); v1 = fmaxf(v1, 0.f);
                v2 = fmaxf(v2, 0.f); v3 = fmaxf(v3, 0.f);
            }
            if (r0 < M)
                *(float2*)&out[(size_t)r0 * DIM + col] = make_float2(v0, v1);
            if (r0 + 8 < M)
                *(float2*)&out[(size_t)(r0 + 8) * DIM + col] = make_float2(v2, v3);
        }
    }
}

// ---------------- launcher ----------------
extern "C" void kernel_launch(void* const* d_in, const int* in_sizes, int n_in,
                              void* d_out, int out_size) {
    const int*   x      = (const int*)  d_in[0];
    const int*   eidx   = (const int*)  d_in[1];
    const int*   etyp   = (const int*)  d_in[2];
    const float* table  = (const float*)d_in[3];
    const float* comp1  = (const float*)d_in[4];
    const float* bases1 = (const float*)d_in[5];
    const float* root1  = (const float*)d_in[6];
    const float* bias1  = (const float*)d_in[7];
    const float* comp2  = (const float*)d_in[8];
    const float* bases2 = (const float*)d_in[9];
    const float* root2  = (const float*)d_in[10];
    const float* bias2  = (const float*)d_in[11];

    const int E = in_sizes[2];
    const int N = in_sizes[0];
    const int* e_src = eidx;
    const int* e_dst = eidx + E;
    float* out = (float*)d_out;

    float *h0, *h1, *Tm, *Bp1, *Bp2;
    cudaGetSymbolAddress((void**)&h0,  g_h0);
    cudaGetSymbolAddress((void**)&h1,  g_h1);
    cudaGetSymbolAddress((void**)&Tm,  g_T);
    cudaGetSymbolAddress((void**)&Bp1, g_Bp1);
    cudaGetSymbolAddress((void**)&Bp2, g_Bp2);

    cudaFuncSetAttribute(gemm_tc,
                         cudaFuncAttributeMaxDynamicSharedMemorySize, GEMM_SMEM);

    int eBlocks = (E + 255) / 256;
    int zBlocks = (N * NREL + 255) / 256;
    int sBlocks = (N + 1023) / 1024;

    // CSR build
    zero_nr_kernel<<<zBlocks, 256>>>();
    hist_kernel<<<eBlocks, 256>>>(e_dst, etyp, E);
    csr_part1<<<sBlocks, 1024>>>();
    csr_part2<<<1, 32>>>(sBlocks);
    csr_part3<<<sBlocks, 1024>>>();
    scatter_kernel<<<eBlocks, 256>>>(e_src, e_dst, etyp, E);

    // embedding + weight prep
    embed_kernel<<<N, DIM>>>(x, table);
    prep_b_kernel<<<KTOT, DIM>>>(bases1, root1, Bp1);
    prep_b_kernel<<<KTOT, DIM>>>(bases2, root2, Bp2);

    // layer 1: chunked agg -> gemm so T chunk stays L2-resident
    for (int c = 0; c < N; c += CHUNK) {
        int cnt = (N - c < CHUNK) ? (N - c) : CHUNK;
        agg_kernel<<<cnt, 64>>>(h0, comp1, c);
        gemm_tc<<<(cnt + 127) / 128, 256, GEMM_SMEM>>>(Tm, h0, Bp1, bias1,
                                                       h1, N, 1, c);
    }

    // layer 2
    for (int c = 0; c < N; c += CHUNK) {
        int cnt = (N - c < CHUNK) ? (N - c) : CHUNK;
        agg_kernel<<<cnt, 64>>>(h1, comp2, c);
        gemm_tc<<<(cnt + 127) / 128, 256, GEMM_SMEM>>>(Tm, h1, Bp2, bias2,
                                                       out, N, 0, c);
    }
}